// round 15
// baseline (speedup 1.0000x reference)
#include <cuda_runtime.h>

#define LEAK 0.2f
constexpr int B_  = 2;
constexpr int C_  = 16;
constexpr int VOL = 96 * 96 * 96;
constexpr int PLN = 96 * 96;
constexpr int DVF = 48;

typedef unsigned long long pk_t;

// Scratch (device globals per harness rules).
__device__ float g_warped[(size_t)B_ * C_ * VOL];  // warped src; later fsum
__device__ float g_corr[(size_t)B_ * 27 * VOL];    // cost volume
__device__ float g_facc[(size_t)B_ * C_ * VOL];    // conv1 out (f)

__device__ __forceinline__ float lrelu(float v) { return v > 0.f ? v : LEAK * v; }

__device__ __forceinline__ pk_t pack2(float lo, float hi) {
    pk_t r; asm("mov.b64 %0, {%1,%2};" : "=l"(r) : "f"(lo), "f"(hi)); return r;
}
__device__ __forceinline__ void unpack2(pk_t p, float& lo, float& hi) {
    asm("mov.b64 {%0,%1}, %2;" : "=f"(lo), "=f"(hi) : "l"(p));
}
__device__ __forceinline__ pk_t ffma2(pk_t a, pk_t b, pk_t c) {
    pk_t d; asm("fma.rn.f32x2 %0, %1, %2, %3;" : "=l"(d) : "l"(a), "l"(b), "l"(c));
    return d;
}
__device__ __forceinline__ float fsel(bool p, float v) { return p ? v : 0.f; }

// ---------------------------------------------------------------------------
// K1: trilinear upsample of dvf (48^3 -> 96^3, align_corners) + warp source
// ---------------------------------------------------------------------------
__global__ void warp_kernel(const float* __restrict__ src,
                            const float* __restrict__ dvf)
{
    int idx = blockIdx.x * blockDim.x + threadIdx.x;
    if (idx >= B_ * VOL) return;
    int b = idx / VOL;
    int r = idx - b * VOL;
    int z = r / PLN;
    int y = (r / 96) % 96;
    int x = r % 96;

    const float sc = 47.0f / 95.0f;
    float pz = z * sc, py = y * sc, px = x * sc;
    int z0 = (int)pz, y0 = (int)py, x0 = (int)px;
    int z1 = min(z0 + 1, DVF - 1), y1 = min(y0 + 1, DVF - 1), x1 = min(x0 + 1, DVF - 1);
    float wz = pz - (float)z0, wy = py - (float)y0, wx = px - (float)x0;

    const float* dv = dvf + (size_t)b * 3 * DVF * DVF * DVF;
    float flow[3];
#pragma unroll
    for (int cc = 0; cc < 3; cc++) {
        const float* p = dv + (size_t)cc * DVF * DVF * DVF;
        float v000 = __ldg(p + (z0 * 48 + y0) * 48 + x0);
        float v001 = __ldg(p + (z0 * 48 + y0) * 48 + x1);
        float v010 = __ldg(p + (z0 * 48 + y1) * 48 + x0);
        float v011 = __ldg(p + (z0 * 48 + y1) * 48 + x1);
        float v100 = __ldg(p + (z1 * 48 + y0) * 48 + x0);
        float v101 = __ldg(p + (z1 * 48 + y0) * 48 + x1);
        float v110 = __ldg(p + (z1 * 48 + y1) * 48 + x0);
        float v111 = __ldg(p + (z1 * 48 + y1) * 48 + x1);
        float v00 = v000 * (1.f - wx) + v001 * wx;
        float v01 = v010 * (1.f - wx) + v011 * wx;
        float v10 = v100 * (1.f - wx) + v101 * wx;
        float v11 = v110 * (1.f - wx) + v111 * wx;
        float v0 = v00 * (1.f - wy) + v01 * wy;
        float v1 = v10 * (1.f - wy) + v11 * wy;
        flow[cc] = v0 * (1.f - wz) + v1 * wz;
    }

    float zc = (float)z + flow[0];
    float yc = (float)y + flow[1];
    float xc = (float)x + flow[2];
    float zf = floorf(zc), yf = floorf(yc), xf = floorf(xc);
    float fz = zc - zf, fy = yc - yf, fx = xc - xf;
    int iz0 = (int)zf, iy0 = (int)yf, ix0 = (int)xf;

    int   zi[2] = { iz0, iz0 + 1 };
    int   yi[2] = { iy0, iy0 + 1 };
    int   xi[2] = { ix0, ix0 + 1 };
    float wzv[2] = { 1.f - fz, fz };
    float wyv[2] = { 1.f - fy, fy };
    float wxv[2] = { 1.f - fx, fx };

    int   idx8[8];
    float w8[8];
    int j = 0;
#pragma unroll
    for (int a = 0; a < 2; a++)
#pragma unroll
        for (int bb = 0; bb < 2; bb++)
#pragma unroll
            for (int c2 = 0; c2 < 2; c2++) {
                int zz = zi[a], yy = yi[bb], xx = xi[c2];
                bool valid = (zz >= 0 && zz < 96 && yy >= 0 && yy < 96 &&
                              xx >= 0 && xx < 96);
                int zcl = min(max(zz, 0), 95);
                int ycl = min(max(yy, 0), 95);
                int xcl = min(max(xx, 0), 95);
                idx8[j] = (zcl * 96 + ycl) * 96 + xcl;
                w8[j] = valid ? (wzv[a] * wyv[bb] * wxv[c2]) : 0.f;
                j++;
            }

    const float* sb = src + (size_t)b * C_ * VOL;
    float* ob = g_warped + (size_t)b * C_ * VOL + r;
#pragma unroll
    for (int c = 0; c < C_; c++) {
        const float* sp = sb + (size_t)c * VOL;
        float v = 0.f;
#pragma unroll
        for (int k = 0; k < 8; k++) v = fmaf(w8[k], __ldg(sp + idx8[k]), v);
        ob[(size_t)c * VOL] = v;
    }
}

// ---------------------------------------------------------------------------
// K2: 27-shift cost volume, f32x2 packed, 2 x per thread, branchless inner.
// ---------------------------------------------------------------------------
__global__ void __launch_bounds__(256, 2) corrp_kernel(const float* __restrict__ tgt)
{
    constexpr int ZCC = 12, NZCC = 96 / ZCC;
    int bz = blockIdx.z;
    int zc = bz % NZCC; bz /= NZCC;
    int b = bz;
    int tx = threadIdx.x, ty = threadIdx.y;
    int gx = blockIdx.x * 32 + tx * 2;
    int y  = blockIdx.y * 16 + ty;
    int zs = zc * ZCC;

    const float* wb = g_warped + (size_t)b * C_ * VOL;
    const float* tb = tgt + (size_t)b * C_ * VOL;

    int offl = (gx > 0)  ? -1 : 0;   // loop-invariant edge offsets (in-bounds)
    int offr = (gx < 94) ?  2 : 1;   // fall back to in-row elem, selected to 0
    bool vxm = (gx > 0), vxp = (gx < 94);

    for (int z = zs; z < zs + ZCC; z++) {
        // Hoist the 9 (dz,dy) validity masks + clamped plane offsets.
        size_t soff[9];
        bool   svld[9];
#pragma unroll
        for (int dz = 0; dz < 3; dz++) {
#pragma unroll
            for (int dy = 0; dy < 3; dy++) {
                int zz = z + dz - 1, yy = y + dy - 1;
                bool v = (unsigned)zz <= 95u && (unsigned)yy <= 95u;
                int zzc = min(max(zz, 0), 95);
                int yyc = min(max(yy, 0), 95);
                soff[dz * 3 + dy] = (size_t)zzc * PLN + yyc * 96 + gx;
                svld[dz * 3 + dy] = v;
            }
        }

        pk_t acc[27];
#pragma unroll
        for (int s = 0; s < 27; s++) acc[s] = 0ull;

#pragma unroll 1
        for (int ch = 0; ch < C_; ch++) {
            pk_t t2 = *(const pk_t*)(tb + (size_t)ch * VOL + (size_t)z * PLN + y * 96 + gx);
            const float* wc = wb + (size_t)ch * VOL;
#pragma unroll
            for (int q = 0; q < 9; q++) {
                const float* pr = wc + soff[q];
                float2 m = __ldg((const float2*)pr);
                float vlr = __ldg(pr + offl);
                float vrr = __ldg(pr + offr);
                bool v = svld[q];
                float m0 = fsel(v, m.x);
                float m1 = fsel(v, m.y);
                float vl = fsel(v && vxm, vlr);
                float vr = fsel(v && vxp, vrr);
                pk_t pL = pack2(vl, m0);
                pk_t pC = pack2(m0, m1);
                pk_t pR = pack2(m1, vr);
                int s = q * 3;
                acc[s]     = ffma2(t2, pL, acc[s]);
                acc[s + 1] = ffma2(t2, pC, acc[s + 1]);
                acc[s + 2] = ffma2(t2, pR, acc[s + 2]);
            }
        }

        float* op = g_corr + (size_t)b * 27 * VOL + (size_t)z * PLN + y * 96 + gx;
#pragma unroll
        for (int s = 0; s < 27; s++) {
            float lo, hi;
            unpack2(acc[s], lo, hi);
            lo = lrelu(lo * 0.0625f);
            hi = lrelu(hi * 0.0625f);
            *(float2*)(op + (size_t)s * VOL) = make_float2(lo, hi);
        }
    }
}

// ---------------------------------------------------------------------------
// Packed 3x3x3 conv, z-ring, XPT=4 (2 packed pairs), duplicated weights in smem,
// branchless inner loop. Block: (8,16) = 128 threads -> 32x16 xy tile.
// __launch_bounds__(128,5): 20 warps/SM for latency hiding.
// ---------------------------------------------------------------------------
template<int CIN0, int CIN1, int CIN2, int COUT_TOT, int COG, int COUT_STORE,
         int ZCc, bool RES>
__global__ void __launch_bounds__(128, 5) convp_kernel(
    const float* __restrict__ in0, const float* __restrict__ in1,
    const float* __restrict__ in2,
    const float* __restrict__ w, const float* __restrict__ bias,
    float* __restrict__ out, const float* __restrict__ res)
{
    constexpr int CTOT = CIN0 + CIN1 + CIN2;
    constexpr int NCG  = (COUT_TOT + COG - 1) / COG;
    constexpr int NZCc = 96 / ZCc;
    constexpr int COGP = (COG & 1) ? COG + 1 : COG;
    constexpr int COGH = COG / 2;
    extern __shared__ char smraw[];
    pk_t* swgt = (pk_t*)smraw;   // [ci][t9][kz3][COGP] duplicated (w,w)

    int bz = blockIdx.z;
    int zc = bz % NZCc; bz /= NZCc;
    int cg = bz % NCG;  bz /= NCG;
    int b  = bz;
    int co0 = cg * COG;

    int tid = threadIdx.y * 8 + threadIdx.x;
    for (int i = tid; i < CTOT * 27 * COGP; i += 128) {
        int co = i % COGP;
        int r  = i / COGP;
        int kz = r % 3;
        int t  = (r / 3) % 9;
        int ci = r / 27;
        int cog = co0 + co;
        float wv = (co < COG && cog < COUT_STORE)
            ? __ldg(w + ((size_t)cog * CTOT + ci) * 27 + kz * 9 + t) : 0.f;
        swgt[i] = pack2(wv, wv);
    }
    __syncthreads();

    int gx = blockIdx.x * 32 + threadIdx.x * 4;
    int y  = blockIdx.y * 16 + threadIdx.y;
    int zs = zc * ZCc;

    bool vxm = (gx > 0), vxp = (gx < 92);
    int offl = vxm ? -1 : 0;   // in-bounds fallback, value selected to 0
    int offr = vxp ?  4 : 3;

    // Hoisted per-thread y masks and clamped row offsets (dy = 0..2).
    bool vy[3];
    int  roff[3];
#pragma unroll
    for (int dy = 0; dy < 3; dy++) {
        int yy = y + dy - 1;
        vy[dy] = (unsigned)yy <= 95u;
        roff[dy] = min(max(yy, 0), 95) * 96 + gx;
    }

    const float* base0 = in0 + (size_t)b * CIN0 * VOL;
    const float* base1 = (CIN1 > 0) ? in1 + (size_t)b * CIN1 * VOL : nullptr;
    const float* base2 = (CIN2 > 0) ? in2 + (size_t)b * CIN2 * VOL : nullptr;

    pk_t bpk[COG];
#pragma unroll
    for (int co = 0; co < COG; co++) {
        float bv = (co0 + co < COUT_STORE) ? __ldg(bias + co0 + co) : 0.f;
        bpk[co] = pack2(bv, bv);
    }

    pk_t a0[2 * COG], a1[2 * COG], a2[2 * COG];
#pragma unroll
    for (int i = 0; i < 2 * COG; i++) { a0[i] = 0ull; a1[i] = 0ull; a2[i] = 0ull; }

#define KZROW(S, WKZ, P0, P1)                                                  \
    {                                                                          \
        _Pragma("unroll")                                                      \
        for (int h = 0; h < COGH; h++) {                                       \
            ulonglong2 wv = *(const ulonglong2*)((WKZ) + 2 * h);               \
            S[2 * h]           = ffma2(P0, wv.x, S[2 * h]);                    \
            S[COG + 2 * h]     = ffma2(P1, wv.x, S[COG + 2 * h]);              \
            S[2 * h + 1]       = ffma2(P0, wv.y, S[2 * h + 1]);                \
            S[COG + 2 * h + 1] = ffma2(P1, wv.y, S[COG + 2 * h + 1]);          \
        }                                                                      \
        if (COG & 1) {                                                         \
            pk_t wv = (WKZ)[COG - 1];                                          \
            S[COG - 1]     = ffma2(P0, wv, S[COG - 1]);                        \
            S[2 * COG - 1] = ffma2(P1, wv, S[2 * COG - 1]);                    \
        }                                                                      \
    }

#define SEG_LOOP(BASE, CINSEG, CIOFF, AP, AC, AN)                              \
    _Pragma("unroll 1")                                                        \
    for (int ci = 0; ci < (CINSEG); ci++) {                                    \
        const float* p = (BASE) + ((size_t)ci) * VOL + (size_t)z * PLN;        \
        const pk_t* wci = swgt + (size_t)((CIOFF) + ci) * 27 * COGP;           \
        _Pragma("unroll")                                                      \
        for (int dy = 0; dy < 3; dy++) {                                       \
            const float* pr = p + roff[dy];                                    \
            float4 A = __ldg((const float4*)pr);                               \
            float vlr = __ldg(pr + offl);                                      \
            float vrr = __ldg(pr + offr);                                      \
            bool v = vy[dy];                                                   \
            float ax = fsel(v, A.x), ay = fsel(v, A.y);                        \
            float az = fsel(v, A.z), aw = fsel(v, A.w);                        \
            float vl = fsel(v && vxm, vlr);                                    \
            float vr = fsel(v && vxp, vrr);                                    \
            pk_t e0 = pack2(ax, ay), e1 = pack2(az, aw);                       \
            pk_t s0 = pack2(vl, ax);                                           \
            pk_t s1 = pack2(ay, az);                                           \
            pk_t s2 = pack2(aw, vr);                                           \
            _Pragma("unroll")                                                  \
            for (int kx = 0; kx < 3; kx++) {                                   \
                pk_t P0 = (kx == 0) ? s0 : (kx == 1) ? e0 : s1;                \
                pk_t P1 = (kx == 0) ? s1 : (kx == 1) ? e1 : s2;                \
                const pk_t* wt = wci + ((dy * 3 + kx) * 3) * COGP;             \
                KZROW(AN, wt,            P0, P1);                              \
                KZROW(AC, wt + COGP,     P0, P1);                              \
                KZROW(AP, wt + 2 * COGP, P0, P1);                              \
            }                                                                  \
        }                                                                      \
    }

#define CONV_STEP(ZP, AP, AC, AN)                                              \
    {                                                                          \
        int z = (ZP);                                                          \
        if (z >= 0 && z <= 95 && z <= zs + ZCc) {                              \
            SEG_LOOP(base0, CIN0, 0, AP, AC, AN);                              \
            if (CIN1 > 0) { SEG_LOOP(base1, CIN1, CIN0, AP, AC, AN); }         \
            if (CIN2 > 0) { SEG_LOOP(base2, CIN2, CIN0 + CIN1, AP, AC, AN); }  \
        }                                                                      \
        int zo = z - 1;                                                        \
        if (zo >= zs && zo < zs + ZCc) {                                       \
            _Pragma("unroll")                                                  \
            for (int co = 0; co < COG; co++) {                                 \
                if (co0 + co < COUT_STORE) {                                   \
                    size_t off = ((size_t)(b * COUT_STORE + co0 + co)) * VOL + \
                                 (size_t)zo * PLN + y * 96 + gx;               \
                    float o0, o1, o2, o3, blo, bhi;                            \
                    unpack2(bpk[co], blo, bhi);                                \
                    unpack2(AP[co], o0, o1);                                   \
                    unpack2(AP[COG + co], o2, o3);                             \
                    o0 = lrelu(o0 + blo); o1 = lrelu(o1 + bhi);                \
                    o2 = lrelu(o2 + blo); o3 = lrelu(o3 + bhi);                \
                    if (RES) {                                                 \
                        float4 r4 = __ldg((const float4*)(res + off));         \
                        o0 += r4.x; o1 += r4.y; o2 += r4.z; o3 += r4.w;        \
                    }                                                          \
                    *(float4*)(out + off) = make_float4(o0, o1, o2, o3);       \
                }                                                              \
            }                                                                  \
        }                                                                      \
        _Pragma("unroll")                                                      \
        for (int i = 0; i < 2 * COG; i++) AP[i] = 0ull;                        \
    }

    for (int zb = zs - 1; zb <= zs + ZCc; zb += 3) {
        CONV_STEP(zb,     a0, a1, a2);
        CONV_STEP(zb + 1, a1, a2, a0);
        CONV_STEP(zb + 2, a2, a0, a1);
    }
#undef CONV_STEP
#undef SEG_LOOP
#undef KZROW
}

// ---------------------------------------------------------------------------
extern "C" void kernel_launch(void* const* d_in, const int* in_sizes, int n_in,
                              void* d_out, int out_size)
{
    const float* src = (const float*)d_in[0];
    const float* tgt = (const float*)d_in[1];
    const float* dvf = (const float*)d_in[2];
    const float* w1  = (const float*)d_in[3];
    const float* b1  = (const float*)d_in[4];
    const float* w2  = (const float*)d_in[5];
    const float* b2  = (const float*)d_in[6];
    const float* w3  = (const float*)d_in[7];
    const float* b3  = (const float*)d_in[8];
    float* out = (float*)d_out;

    float* warped = nullptr;
    float* corr   = nullptr;
    float* facc   = nullptr;
    cudaGetSymbolAddress((void**)&warped, g_warped);
    cudaGetSymbolAddress((void**)&corr, g_corr);
    cudaGetSymbolAddress((void**)&facc, g_facc);

    const int sm1 = 59 * 27 * 4 * (int)sizeof(pk_t);   // 50976
    const int sm2 = 16 * 27 * 4 * (int)sizeof(pk_t);   // 13824
    const int sm3 = 16 * 27 * 4 * (int)sizeof(pk_t);   // COGP=4 for COG=3

    cudaFuncSetAttribute((const void*)&convp_kernel<16, 27, 16, 16, 4, 16, 24, false>,
                         cudaFuncAttributeMaxDynamicSharedMemorySize, sm1);
    cudaFuncSetAttribute((const void*)&convp_kernel<16, 0, 0, 16, 4, 16, 24, true>,
                         cudaFuncAttributeMaxDynamicSharedMemorySize, sm2);
    cudaFuncSetAttribute((const void*)&convp_kernel<16, 0, 0, 3, 3, 3, 6, false>,
                         cudaFuncAttributeMaxDynamicSharedMemorySize, sm3);

    int nvox = B_ * VOL;
    warp_kernel<<<(nvox + 255) / 256, 256>>>(src, dvf);

    dim3 cblk(16, 16);
    dim3 cgrd(3, 6, 8 * B_);
    corrp_kernel<<<cgrd, cblk>>>(tgt);

    dim3 blk(8, 16);                // 128 threads, 32x16 xy tile
    dim3 g1(3, 6, 4 * 4 * B_);      // ZC=24 (NZC=4) x NCG=4 x B -> 576 blocks
    dim3 g3(3, 6, 16 * 1 * B_);     // ZC=6  (NZC=16) x NCG=1 x B -> 576 blocks

    // conv1 fused over its 3 input segments (src, corr, tgt): 59ch -> 16ch, lrelu
    convp_kernel<16, 27, 16, 16, 4, 16, 24, false>
        <<<g1, blk, sm1>>>(src, corr, tgt, w1, b1, facc, nullptr);
    // conv2 + residual: fsum = f + lrelu(conv(f))
    convp_kernel<16, 0, 0, 16, 4, 16, 24, true>
        <<<g1, blk, sm2>>>(facc, nullptr, nullptr, w2, b2, warped, facc);
    // conv3: 16 -> 3
    convp_kernel<16, 0, 0, 3, 3, 3, 6, false>
        <<<g3, blk, sm3>>>(warped, nullptr, nullptr, w3, b3, out, nullptr);
}

// round 16
// speedup vs baseline: 1.2706x; 1.2706x over previous
#include <cuda_runtime.h>

#define LEAK 0.2f
constexpr int B_  = 2;
constexpr int C_  = 16;
constexpr int VOL = 96 * 96 * 96;
constexpr int PLN = 96 * 96;
constexpr int DVF = 48;

// Padded geometry: z in [-1,96], y in [-1,96], x in [-4,107]; interior at (+1,+1,+4)
constexpr int PW   = 112;            // row stride (floats), 448B = 16B-aligned
constexpr int PPLN = 98 * PW;        // 10976
constexpr size_t PVOL = (size_t)98 * PPLN;  // 1,075,648 floats per channel

typedef unsigned long long pk_t;

// Padded scratch (device globals: zero-initialized; halos never written => stay 0).
__device__ float g_psrc [(size_t)B_ * 16 * PVOL];
__device__ float g_ptgt [(size_t)B_ * 16 * PVOL];
__device__ float g_pwarp[(size_t)B_ * 16 * PVOL];
__device__ float g_pcorr[(size_t)B_ * 27 * PVOL];
__device__ float g_pf   [(size_t)B_ * 16 * PVOL];
__device__ float g_pfsum[(size_t)B_ * 16 * PVOL];

__device__ __forceinline__ size_t pidx(int z, int y, int x) {
    return (size_t)(z + 1) * PPLN + (y + 1) * PW + (x + 4);
}

__device__ __forceinline__ float lrelu(float v) { return v > 0.f ? v : LEAK * v; }

__device__ __forceinline__ pk_t pack2(float lo, float hi) {
    pk_t r; asm("mov.b64 %0, {%1,%2};" : "=l"(r) : "f"(lo), "f"(hi)); return r;
}
__device__ __forceinline__ void unpack2(pk_t p, float& lo, float& hi) {
    asm("mov.b64 {%0,%1}, %2;" : "=f"(lo), "=f"(hi) : "l"(p));
}
__device__ __forceinline__ pk_t ffma2(pk_t a, pk_t b, pk_t c) {
    pk_t d; asm("fma.rn.f32x2 %0, %1, %2, %3;" : "=l"(d) : "l"(a), "l"(b), "l"(c));
    return d;
}

// ---------------------------------------------------------------------------
// K0: copy src/tgt into padded layout (interior only), float4 per thread.
// ---------------------------------------------------------------------------
__global__ void padcpy_kernel(const float* __restrict__ src,
                              const float* __restrict__ tgt)
{
    int idx = blockIdx.x * blockDim.x + threadIdx.x;
    int nquads = B_ * 16 * (VOL / 4);
    if (idx >= 2 * nquads) return;
    int t = idx / nquads;         // 0 = src, 1 = tgt
    int r = idx - t * nquads;
    int q = r % (VOL / 4);        // quad within volume
    int bc = r / (VOL / 4);       // b*16 + c
    int x4 = (q % 24) * 4;
    int y  = (q / 24) % 96;
    int z  = q / (24 * 96);

    const float* in = (t == 0 ? src : tgt) + (size_t)bc * VOL;
    float* out = (t == 0 ? g_psrc : g_ptgt) + (size_t)bc * PVOL;
    float4 v = __ldg((const float4*)(in + (size_t)z * PLN + y * 96 + x4));
    *(float4*)(out + pidx(z, y, x4)) = v;
}

// ---------------------------------------------------------------------------
// K1: trilinear upsample of dvf (48^3 -> 96^3, align_corners) + warp source.
// Writes warped into padded g_pwarp.
// ---------------------------------------------------------------------------
__global__ void warp_kernel(const float* __restrict__ src,
                            const float* __restrict__ dvf)
{
    int idx = blockIdx.x * blockDim.x + threadIdx.x;
    if (idx >= B_ * VOL) return;
    int b = idx / VOL;
    int r = idx - b * VOL;
    int z = r / PLN;
    int y = (r / 96) % 96;
    int x = r % 96;

    const float sc = 47.0f / 95.0f;
    float pz = z * sc, py = y * sc, px = x * sc;
    int z0 = (int)pz, y0 = (int)py, x0 = (int)px;
    int z1 = min(z0 + 1, DVF - 1), y1 = min(y0 + 1, DVF - 1), x1 = min(x0 + 1, DVF - 1);
    float wz = pz - (float)z0, wy = py - (float)y0, wx = px - (float)x0;

    const float* dv = dvf + (size_t)b * 3 * DVF * DVF * DVF;
    float flow[3];
#pragma unroll
    for (int cc = 0; cc < 3; cc++) {
        const float* p = dv + (size_t)cc * DVF * DVF * DVF;
        float v000 = __ldg(p + (z0 * 48 + y0) * 48 + x0);
        float v001 = __ldg(p + (z0 * 48 + y0) * 48 + x1);
        float v010 = __ldg(p + (z0 * 48 + y1) * 48 + x0);
        float v011 = __ldg(p + (z0 * 48 + y1) * 48 + x1);
        float v100 = __ldg(p + (z1 * 48 + y0) * 48 + x0);
        float v101 = __ldg(p + (z1 * 48 + y0) * 48 + x1);
        float v110 = __ldg(p + (z1 * 48 + y1) * 48 + x0);
        float v111 = __ldg(p + (z1 * 48 + y1) * 48 + x1);
        float v00 = v000 * (1.f - wx) + v001 * wx;
        float v01 = v010 * (1.f - wx) + v011 * wx;
        float v10 = v100 * (1.f - wx) + v101 * wx;
        float v11 = v110 * (1.f - wx) + v111 * wx;
        float v0 = v00 * (1.f - wy) + v01 * wy;
        float v1 = v10 * (1.f - wy) + v11 * wy;
        flow[cc] = v0 * (1.f - wz) + v1 * wz;
    }

    float zc = (float)z + flow[0];
    float yc = (float)y + flow[1];
    float xc = (float)x + flow[2];
    float zf = floorf(zc), yf = floorf(yc), xf = floorf(xc);
    float fz = zc - zf, fy = yc - yf, fx = xc - xf;
    int iz0 = (int)zf, iy0 = (int)yf, ix0 = (int)xf;

    int   zi[2] = { iz0, iz0 + 1 };
    int   yi[2] = { iy0, iy0 + 1 };
    int   xi[2] = { ix0, ix0 + 1 };
    float wzv[2] = { 1.f - fz, fz };
    float wyv[2] = { 1.f - fy, fy };
    float wxv[2] = { 1.f - fx, fx };

    int   idx8[8];
    float w8[8];
    int j = 0;
#pragma unroll
    for (int a = 0; a < 2; a++)
#pragma unroll
        for (int bb = 0; bb < 2; bb++)
#pragma unroll
            for (int c2 = 0; c2 < 2; c2++) {
                int zz = zi[a], yy = yi[bb], xx = xi[c2];
                bool valid = (zz >= 0 && zz < 96 && yy >= 0 && yy < 96 &&
                              xx >= 0 && xx < 96);
                int zcl = min(max(zz, 0), 95);
                int ycl = min(max(yy, 0), 95);
                int xcl = min(max(xx, 0), 95);
                idx8[j] = (zcl * 96 + ycl) * 96 + xcl;
                w8[j] = valid ? (wzv[a] * wyv[bb] * wxv[c2]) : 0.f;
                j++;
            }

    const float* sb = src + (size_t)b * C_ * VOL;
    float* ob = g_pwarp + (size_t)b * C_ * PVOL + pidx(z, y, x);
#pragma unroll
    for (int c = 0; c < C_; c++) {
        const float* sp = sb + (size_t)c * VOL;
        float v = 0.f;
#pragma unroll
        for (int k = 0; k < 8; k++) v = fmaf(w8[k], __ldg(sp + idx8[k]), v);
        ob[(size_t)c * PVOL] = v;
    }
}

// ---------------------------------------------------------------------------
// K2: 27-shift cost volume, f32x2 packed, 2 x per thread, guard-free (padded).
// ---------------------------------------------------------------------------
__global__ void __launch_bounds__(256, 2) corrp_kernel(const float* __restrict__ tgt)
{
    constexpr int ZCC = 12, NZCC = 96 / ZCC;
    int bz = blockIdx.z;
    int zc = bz % NZCC; bz /= NZCC;
    int b = bz;
    int tx = threadIdx.x, ty = threadIdx.y;
    int gx = blockIdx.x * 32 + tx * 2;
    int y  = blockIdx.y * 16 + ty;
    int zs = zc * ZCC;

    const float* wb = g_pwarp + (size_t)b * C_ * PVOL;
    const float* tb = tgt + (size_t)b * C_ * VOL;

    for (int z = zs; z < zs + ZCC; z++) {
        pk_t acc[27];
#pragma unroll
        for (int s = 0; s < 27; s++) acc[s] = 0ull;

#pragma unroll 1
        for (int ch = 0; ch < C_; ch++) {
            pk_t t2 = *(const pk_t*)(tb + (size_t)ch * VOL + (size_t)z * PLN + y * 96 + gx);
            const float* wc = wb + (size_t)ch * PVOL + pidx(z - 1, y - 1, gx);
#pragma unroll
            for (int dz = 0; dz < 3; dz++) {
#pragma unroll
                for (int dy = 0; dy < 3; dy++) {
                    const float* pr = wc + (size_t)dz * PPLN + dy * PW;
                    float2 m = __ldg((const float2*)pr);
                    float vl = __ldg(pr - 1);
                    float vr = __ldg(pr + 2);
                    pk_t pL = pack2(vl, m.x);
                    pk_t pC = pack2(m.x, m.y);
                    pk_t pR = pack2(m.y, vr);
                    int s = (dz * 3 + dy) * 3;
                    acc[s]     = ffma2(t2, pL, acc[s]);
                    acc[s + 1] = ffma2(t2, pC, acc[s + 1]);
                    acc[s + 2] = ffma2(t2, pR, acc[s + 2]);
                }
            }
        }

        float* op = g_pcorr + (size_t)b * 27 * PVOL + pidx(z, y, gx);
#pragma unroll
        for (int s = 0; s < 27; s++) {
            float lo, hi;
            unpack2(acc[s], lo, hi);
            lo = lrelu(lo * 0.0625f);
            hi = lrelu(hi * 0.0625f);
            *(float2*)(op + (size_t)s * PVOL) = make_float2(lo, hi);
        }
    }
}

// ---------------------------------------------------------------------------
// Packed 3x3x3 conv on PADDED inputs: guard-free inner loop.
// z-ring, XPT=4 (2 packed pairs), COG couts, duplicated weights in smem.
// Block (8,32) -> 32x32 xy tile. OUTPAD: store to padded layout.
// ---------------------------------------------------------------------------
template<int CIN0, int CIN1, int CIN2, int COUT_TOT, int COG, int COUT_STORE,
         int ZCc, bool RES, bool OUTPAD>
__global__ void __launch_bounds__(256, 2) convp_kernel(
    const float* __restrict__ in0, const float* __restrict__ in1,
    const float* __restrict__ in2,
    const float* __restrict__ w, const float* __restrict__ bias,
    float* __restrict__ out, const float* __restrict__ res)
{
    constexpr int CTOT = CIN0 + CIN1 + CIN2;
    constexpr int NCG  = (COUT_TOT + COG - 1) / COG;
    constexpr int NZCc = 96 / ZCc;
    constexpr int COGP = (COG & 1) ? COG + 1 : COG;
    constexpr int COGH = COG / 2;
    extern __shared__ char smraw[];
    pk_t* swgt = (pk_t*)smraw;   // [ci][t9][kz3][COGP] duplicated (w,w)

    int bz = blockIdx.z;
    int zc = bz % NZCc; bz /= NZCc;
    int cg = bz % NCG;  bz /= NCG;
    int b  = bz;
    int co0 = cg * COG;

    int tid = threadIdx.y * 8 + threadIdx.x;
    for (int i = tid; i < CTOT * 27 * COGP; i += 256) {
        int co = i % COGP;
        int r  = i / COGP;
        int kz = r % 3;
        int t  = (r / 3) % 9;
        int ci = r / 27;
        int cog = co0 + co;
        float wv = (co < COG && cog < COUT_STORE)
            ? __ldg(w + ((size_t)cog * CTOT + ci) * 27 + kz * 9 + t) : 0.f;
        swgt[i] = pack2(wv, wv);
    }
    __syncthreads();

    int gx = blockIdx.x * 32 + threadIdx.x * 4;
    int y  = blockIdx.y * 32 + threadIdx.y;
    int zs = zc * ZCc;

    const float* base0 = in0 + (size_t)b * CIN0 * PVOL;
    const float* base1 = (CIN1 > 0) ? in1 + (size_t)b * CIN1 * PVOL : nullptr;
    const float* base2 = (CIN2 > 0) ? in2 + (size_t)b * CIN2 * PVOL : nullptr;

    pk_t bpk[COG];
#pragma unroll
    for (int co = 0; co < COG; co++) {
        float bv = (co0 + co < COUT_STORE) ? __ldg(bias + co0 + co) : 0.f;
        bpk[co] = pack2(bv, bv);
    }

    pk_t a0[2 * COG], a1[2 * COG], a2[2 * COG];
#pragma unroll
    for (int i = 0; i < 2 * COG; i++) { a0[i] = 0ull; a1[i] = 0ull; a2[i] = 0ull; }

#define KZROW(S, WKZ, P0, P1)                                                  \
    {                                                                          \
        _Pragma("unroll")                                                      \
        for (int h = 0; h < COGH; h++) {                                       \
            ulonglong2 wv = *(const ulonglong2*)((WKZ) + 2 * h);               \
            S[2 * h]           = ffma2(P0, wv.x, S[2 * h]);                    \
            S[COG + 2 * h]     = ffma2(P1, wv.x, S[COG + 2 * h]);              \
            S[2 * h + 1]       = ffma2(P0, wv.y, S[2 * h + 1]);                \
            S[COG + 2 * h + 1] = ffma2(P1, wv.y, S[COG + 2 * h + 1]);          \
        }                                                                      \
        if (COG & 1) {                                                         \
            pk_t wv = (WKZ)[COG - 1];                                          \
            S[COG - 1]     = ffma2(P0, wv, S[COG - 1]);                        \
            S[2 * COG - 1] = ffma2(P1, wv, S[2 * COG - 1]);                    \
        }                                                                      \
    }

#define SEG_LOOP(BASE, CINSEG, CIOFF, AP, AC, AN)                              \
    _Pragma("unroll 1")                                                        \
    for (int ci = 0; ci < (CINSEG); ci++) {                                    \
        const float* p = (BASE) + ((size_t)ci) * PVOL +                        \
                         (size_t)(z + 1) * PPLN + y * PW + (gx + 4);           \
        const pk_t* wci = swgt + (size_t)((CIOFF) + ci) * 27 * COGP;           \
        _Pragma("unroll")                                                      \
        for (int dy = 0; dy < 3; dy++) {                                       \
            const float* pr = p + dy * PW;  /* rows y-1, y, y+1 (padded) */    \
            float4 A = __ldg((const float4*)pr);                               \
            float vl = __ldg(pr - 1);                                          \
            float vr = __ldg(pr + 4);                                          \
            pk_t e0 = pack2(A.x, A.y), e1 = pack2(A.z, A.w);                   \
            pk_t s0 = pack2(vl, A.x);                                          \
            pk_t s1 = pack2(A.y, A.z);                                         \
            pk_t s2 = pack2(A.w, vr);                                          \
            _Pragma("unroll")                                                  \
            for (int kx = 0; kx < 3; kx++) {                                   \
                pk_t P0 = (kx == 0) ? s0 : (kx == 1) ? e0 : s1;                \
                pk_t P1 = (kx == 0) ? s1 : (kx == 1) ? e1 : s2;                \
                const pk_t* wt = wci + ((dy * 3 + kx) * 3) * COGP;             \
                KZROW(AN, wt,            P0, P1);                              \
                KZROW(AC, wt + COGP,     P0, P1);                              \
                KZROW(AP, wt + 2 * COGP, P0, P1);                              \
            }                                                                  \
        }                                                                      \
    }

#define CONV_STEP(ZP, AP, AC, AN)                                              \
    {                                                                          \
        int z = (ZP);                                                          \
        if (z <= zs + ZCc) {  /* padded z-halo: no bounds check needed */      \
            SEG_LOOP(base0, CIN0, 0, AP, AC, AN);                              \
            if (CIN1 > 0) { SEG_LOOP(base1, CIN1, CIN0, AP, AC, AN); }         \
            if (CIN2 > 0) { SEG_LOOP(base2, CIN2, CIN0 + CIN1, AP, AC, AN); }  \
        }                                                                      \
        int zo = z - 1;                                                        \
        if (zo >= zs && zo < zs + ZCc) {                                       \
            _Pragma("unroll")                                                  \
            for (int co = 0; co < COG; co++) {                                 \
                if (co0 + co < COUT_STORE) {                                   \
                    size_t off;                                                \
                    if (OUTPAD)                                                \
                        off = ((size_t)(b * COUT_STORE + co0 + co)) * PVOL +   \
                              (size_t)(zo + 1) * PPLN + (y + 1) * PW + (gx + 4);\
                    else                                                       \
                        off = ((size_t)(b * COUT_STORE + co0 + co)) * VOL +    \
                              (size_t)zo * PLN + y * 96 + gx;                  \
                    float o0, o1, o2, o3, blo, bhi;                            \
                    unpack2(bpk[co], blo, bhi);                                \
                    unpack2(AP[co], o0, o1);                                   \
                    unpack2(AP[COG + co], o2, o3);                             \
                    o0 = lrelu(o0 + blo); o1 = lrelu(o1 + bhi);                \
                    o2 = lrelu(o2 + blo); o3 = lrelu(o3 + bhi);                \
                    if (RES) {                                                 \
                        float4 r4 = __ldg((const float4*)(res + off));         \
                        o0 += r4.x; o1 += r4.y; o2 += r4.z; o3 += r4.w;        \
                    }                                                          \
                    *(float4*)(out + off) = make_float4(o0, o1, o2, o3);       \
                }                                                              \
            }                                                                  \
        }                                                                      \
        _Pragma("unroll")                                                      \
        for (int i = 0; i < 2 * COG; i++) AP[i] = 0ull;                        \
    }

    for (int zb = zs - 1; zb <= zs + ZCc; zb += 3) {
        CONV_STEP(zb,     a0, a1, a2);
        CONV_STEP(zb + 1, a1, a2, a0);
        CONV_STEP(zb + 2, a2, a0, a1);
    }
#undef CONV_STEP
#undef SEG_LOOP
#undef KZROW
}

// ---------------------------------------------------------------------------
extern "C" void kernel_launch(void* const* d_in, const int* in_sizes, int n_in,
                              void* d_out, int out_size)
{
    const float* src = (const float*)d_in[0];
    const float* tgt = (const float*)d_in[1];
    const float* dvf = (const float*)d_in[2];
    const float* w1  = (const float*)d_in[3];
    const float* b1  = (const float*)d_in[4];
    const float* w2  = (const float*)d_in[5];
    const float* b2  = (const float*)d_in[6];
    const float* w3  = (const float*)d_in[7];
    const float* b3  = (const float*)d_in[8];
    float* out = (float*)d_out;

    float *psrc = nullptr, *ptgt = nullptr, *pcorr = nullptr;
    float *pf = nullptr, *pfsum = nullptr;
    cudaGetSymbolAddress((void**)&psrc, g_psrc);
    cudaGetSymbolAddress((void**)&ptgt, g_ptgt);
    cudaGetSymbolAddress((void**)&pcorr, g_pcorr);
    cudaGetSymbolAddress((void**)&pf, g_pf);
    cudaGetSymbolAddress((void**)&pfsum, g_pfsum);

    const int sm1 = 59 * 27 * 4 * (int)sizeof(pk_t);   // 50976
    const int sm2 = 16 * 27 * 4 * (int)sizeof(pk_t);   // 13824
    const int sm3 = 16 * 27 * 4 * (int)sizeof(pk_t);   // COGP=4 for COG=3

    cudaFuncSetAttribute((const void*)&convp_kernel<16, 27, 16, 16, 4, 16, 24, false, true>,
                         cudaFuncAttributeMaxDynamicSharedMemorySize, sm1);
    cudaFuncSetAttribute((const void*)&convp_kernel<16, 0, 0, 16, 4, 16, 24, true, true>,
                         cudaFuncAttributeMaxDynamicSharedMemorySize, sm2);
    cudaFuncSetAttribute((const void*)&convp_kernel<16, 0, 0, 3, 3, 3, 6, false, false>,
                         cudaFuncAttributeMaxDynamicSharedMemorySize, sm3);

    int nvox = B_ * VOL;

    // Stage src/tgt into padded layout
    int nq = 2 * B_ * 16 * (VOL / 4);
    padcpy_kernel<<<(nq + 255) / 256, 256>>>(src, tgt);

    warp_kernel<<<(nvox + 255) / 256, 256>>>(src, dvf);

    dim3 cblk(16, 16);
    dim3 cgrd(3, 6, 8 * B_);
    corrp_kernel<<<cgrd, cblk>>>(tgt);

    dim3 blk(8, 32);
    dim3 g1(3, 3, 4 * 4 * B_);    // ZC=24 (NZC=4) x NCG=4 x B -> 288 blocks (1 wave)
    dim3 g3(3, 3, 16 * 1 * B_);   // ZC=6  (NZC=16) x NCG=1 x B -> 288 blocks

    // conv1 fused over its 3 padded input segments (psrc, pcorr, ptgt) -> pf (padded)
    convp_kernel<16, 27, 16, 16, 4, 16, 24, false, true>
        <<<g1, blk, sm1>>>(psrc, pcorr, ptgt, w1, b1, pf, nullptr);
    // conv2 + residual: pfsum = pf + lrelu(conv(pf))  (padded)
    convp_kernel<16, 0, 0, 16, 4, 16, 24, true, true>
        <<<g1, blk, sm2>>>(pf, nullptr, nullptr, w2, b2, pfsum, pf);
    // conv3: 16 -> 3, store to unpadded harness output
    convp_kernel<16, 0, 0, 3, 3, 3, 6, false, false>
        <<<g3, blk, sm3>>>(pfsum, nullptr, nullptr, w3, b3, out, nullptr);
}